// round 3
// baseline (speedup 1.0000x reference)
#include <cuda_runtime.h>
#include <cuda_bf16.h>
#include <cstdint>

// out[n,0,p] = -sqrt(max(||e_n||^2 + ||p_p||^2 - 2 e_n.p_p, 1e-12))
// N=500000, P=256, D=128.
// sm_103 (no 'a' features in this build!): ldmatrix + mma.sync bf16 HMMA path.
// Persistent CTAs; prototypes resident in SMEM; double-buffered A tiles;
// fused distance epilogue. Memory-bound by design (~768 MB traffic).

static constexpr int kD = 128;
static constexpr int kP = 256;
static constexpr int kTM = 128;          // embedding rows per tile
static constexpr int kThreads = 256;     // 8 warps: 4 (M) x 2 (N)

static constexpr uint32_t ROWB = 272;    // smem row stride: 128 bf16 (256B) + 16B pad
static constexpr uint32_t OFF_E2 = 0;                       // 2 x 128 f32
static constexpr uint32_t OFF_P2 = 1024;                    // 256 f32
static constexpr uint32_t OFF_A  = 2048;                    // 2 x 128 x ROWB
static constexpr uint32_t A_BUF  = 128u * ROWB;             // 34816
static constexpr uint32_t OFF_B  = OFF_A + 2u * A_BUF;      // 71680
static constexpr uint32_t SMEM_TOTAL = OFF_B + 256u * ROWB; // 141312

__device__ __forceinline__ uint32_t smem_u32(const void* p) {
    uint32_t a;
    asm("{ .reg .u64 t; cvta.to.shared.u64 t, %1; cvt.u32.u64 %0, t; }" : "=r"(a) : "l"(p));
    return a;
}

__device__ __forceinline__ uint32_t pack2(float a, float b) {
    __nv_bfloat162 h = __floats2bfloat162_rn(a, b);   // a -> low half
    return *reinterpret_cast<uint32_t*>(&h);
}

__device__ __forceinline__ void ldsm_x4(uint32_t addr, uint32_t& r0, uint32_t& r1,
                                        uint32_t& r2, uint32_t& r3) {
    asm volatile("ldmatrix.sync.aligned.m8n8.x4.shared.b16 {%0,%1,%2,%3}, [%4];"
                 : "=r"(r0), "=r"(r1), "=r"(r2), "=r"(r3) : "r"(addr));
}

__device__ __forceinline__ void mma_bf16(float* c, const uint32_t* a,
                                         uint32_t b0, uint32_t b1) {
    asm volatile(
        "mma.sync.aligned.m16n8k16.row.col.f32.bf16.bf16.f32 "
        "{%0,%1,%2,%3}, {%4,%5,%6,%7}, {%8,%9}, {%0,%1,%2,%3};"
        : "+f"(c[0]), "+f"(c[1]), "+f"(c[2]), "+f"(c[3])
        : "r"(a[0]), "r"(a[1]), "r"(a[2]), "r"(a[3]), "r"(b0), "r"(b1));
}

__device__ __forceinline__ float negd(float cross, float s2) {
    float d2 = fmaxf(fmaf(-2.0f, cross, s2), 1e-12f);
    float rt;
    asm("sqrt.approx.f32 %0, %1;" : "=f"(rt) : "f"(d2));
    return -rt;
}

__global__ void __launch_bounds__(kThreads, 1)
proto_kernel(const float* __restrict__ emb, const float* __restrict__ proto,
             float* __restrict__ out, long long nEmb, long long nTiles)
{
    extern __shared__ char smem[];
    const uint32_t sbase = smem_u32(smem);
    const int tid  = (int)threadIdx.x;
    const int lane = tid & 31;
    const int wid  = tid >> 5;
    const int warp_m = wid & 3;   // rows  warp_m*32 .. +32
    const int warp_n = wid >> 2;  // cols  warp_n*128 .. +128

    float* e2s = reinterpret_cast<float*>(smem + OFF_E2);
    float* p2s = reinterpret_cast<float*>(smem + OFF_P2);

    // ---------------- setup: prototypes -> bf16 SMEM + fp32 p2 ----------------
    {
        const int p = tid;  // 256 threads <-> 256 prototype rows
        const float4* src = reinterpret_cast<const float4*>(proto + (size_t)p * kD);
        char* brow = smem + OFF_B + (uint32_t)p * ROWB;
        float acc = 0.f;
#pragma unroll
        for (int j = 0; j < 8; ++j) {
            float4 v0 = __ldg(src + 4 * j + 0);
            float4 v1 = __ldg(src + 4 * j + 1);
            float4 v2 = __ldg(src + 4 * j + 2);
            float4 v3 = __ldg(src + 4 * j + 3);
            acc = fmaf(v0.x, v0.x, acc); acc = fmaf(v0.y, v0.y, acc);
            acc = fmaf(v0.z, v0.z, acc); acc = fmaf(v0.w, v0.w, acc);
            acc = fmaf(v1.x, v1.x, acc); acc = fmaf(v1.y, v1.y, acc);
            acc = fmaf(v1.z, v1.z, acc); acc = fmaf(v1.w, v1.w, acc);
            acc = fmaf(v2.x, v2.x, acc); acc = fmaf(v2.y, v2.y, acc);
            acc = fmaf(v2.z, v2.z, acc); acc = fmaf(v2.w, v2.w, acc);
            acc = fmaf(v3.x, v3.x, acc); acc = fmaf(v3.y, v3.y, acc);
            acc = fmaf(v3.z, v3.z, acc); acc = fmaf(v3.w, v3.w, acc);
            uint4 u0, u1;
            u0.x = pack2(v0.x, v0.y); u0.y = pack2(v0.z, v0.w);
            u0.z = pack2(v1.x, v1.y); u0.w = pack2(v1.z, v1.w);
            u1.x = pack2(v2.x, v2.y); u1.y = pack2(v2.z, v2.w);
            u1.z = pack2(v3.x, v3.y); u1.w = pack2(v3.z, v3.w);
            *reinterpret_cast<uint4*>(brow + 32 * j)      = u0;
            *reinterpret_cast<uint4*>(brow + 32 * j + 16) = u1;
        }
        p2s[p] = acc;
    }

    const long long grid = (long long)gridDim.x;
    const long long t0   = (long long)blockIdx.x;
    const long long T    = (t0 < nTiles) ? ((nTiles - t0 + grid - 1) / grid) : 0;

    // Loader mapping: 2 threads per row, each handles 64 cols (128 B bf16).
    const int lrow  = tid >> 1;
    const int lhalf = tid & 1;

    // ldmatrix per-lane offsets (row-major [m][k] / [n][k], stride ROWB).
    const uint32_t lm_off = (uint32_t)((lane & 7) + ((lane >> 3) & 1) * 8) * ROWB
                          + (uint32_t)((lane >> 4) & 1) * 16u;
    const uint32_t a_base0 = sbase + OFF_A + (uint32_t)(warp_m * 32) * ROWB + lm_off;
    const uint32_t b_base  = sbase + OFF_B + (uint32_t)(warp_n * 128) * ROWB + lm_off;

    // -------- prologue: load tile 0 into buffer 0 --------
    if (T > 0) {
        const long long grow = t0 * kTM + lrow;
        float e2 = 0.f;
        if (grow < nEmb) {
            const float4* src = reinterpret_cast<const float4*>(emb + grow * (long long)kD)
                              + lhalf * 16;
            char* dst = smem + OFF_A + (uint32_t)lrow * ROWB + (uint32_t)lhalf * 128u;
#pragma unroll
            for (int j = 0; j < 4; ++j) {
                float4 v0 = __ldcs(src + 4 * j + 0);
                float4 v1 = __ldcs(src + 4 * j + 1);
                float4 v2 = __ldcs(src + 4 * j + 2);
                float4 v3 = __ldcs(src + 4 * j + 3);
                e2 = fmaf(v0.x, v0.x, e2); e2 = fmaf(v0.y, v0.y, e2);
                e2 = fmaf(v0.z, v0.z, e2); e2 = fmaf(v0.w, v0.w, e2);
                e2 = fmaf(v1.x, v1.x, e2); e2 = fmaf(v1.y, v1.y, e2);
                e2 = fmaf(v1.z, v1.z, e2); e2 = fmaf(v1.w, v1.w, e2);
                e2 = fmaf(v2.x, v2.x, e2); e2 = fmaf(v2.y, v2.y, e2);
                e2 = fmaf(v2.z, v2.z, e2); e2 = fmaf(v2.w, v2.w, e2);
                e2 = fmaf(v3.x, v3.x, e2); e2 = fmaf(v3.y, v3.y, e2);
                e2 = fmaf(v3.z, v3.z, e2); e2 = fmaf(v3.w, v3.w, e2);
                uint4 u0, u1;
                u0.x = pack2(v0.x, v0.y); u0.y = pack2(v0.z, v0.w);
                u0.z = pack2(v1.x, v1.y); u0.w = pack2(v1.z, v1.w);
                u1.x = pack2(v2.x, v2.y); u1.y = pack2(v2.z, v2.w);
                u1.z = pack2(v3.x, v3.y); u1.w = pack2(v3.z, v3.w);
                *reinterpret_cast<uint4*>(dst + 32 * j)      = u0;
                *reinterpret_cast<uint4*>(dst + 32 * j + 16) = u1;
            }
        }
        e2 += __shfl_xor_sync(0xffffffffu, e2, 1);
        if (lhalf == 0) e2s[lrow] = e2;
    }
    __syncthreads();

    // ---------------- main loop ----------------
    for (long long ii = 0; ii < T; ++ii) {
        const int s = (int)(ii & 1);
        const long long tile = t0 + ii * grid;

        // ---- issue next tile's global loads (regs), convert to packed bf16 ----
        uint32_t pk[32];
        float ne2 = 0.f;
        bool nvalid = false;
        if (ii + 1 < T) {
            const long long grow = (tile + grid) * kTM + lrow;
            nvalid = grow < nEmb;
            if (nvalid) {
                const float4* src = reinterpret_cast<const float4*>(emb + grow * (long long)kD)
                                  + lhalf * 16;
                float4 v[16];
#pragma unroll
                for (int i = 0; i < 16; ++i) v[i] = __ldcs(src + i);
#pragma unroll
                for (int i = 0; i < 16; ++i) {
                    ne2 = fmaf(v[i].x, v[i].x, ne2); ne2 = fmaf(v[i].y, v[i].y, ne2);
                    ne2 = fmaf(v[i].z, v[i].z, ne2); ne2 = fmaf(v[i].w, v[i].w, ne2);
                    pk[2 * i]     = pack2(v[i].x, v[i].y);
                    pk[2 * i + 1] = pack2(v[i].z, v[i].w);
                }
            }
        }

        // ---- GEMM: 32x128 per warp from smem buffer s ----
        float acc[2][16][4];
#pragma unroll
        for (int mi = 0; mi < 2; ++mi)
#pragma unroll
            for (int nf = 0; nf < 16; ++nf)
#pragma unroll
                for (int q = 0; q < 4; ++q) acc[mi][nf][q] = 0.f;

        const uint32_t a_base = a_base0 + (uint32_t)s * A_BUF;
#pragma unroll
        for (int ks = 0; ks < 8; ++ks) {
            const uint32_t kb = (uint32_t)(ks * 32);  // k0*2 bytes
            uint32_t a[2][4];
            ldsm_x4(a_base + kb,                 a[0][0], a[0][1], a[0][2], a[0][3]);
            ldsm_x4(a_base + 16u * ROWB + kb,    a[1][0], a[1][1], a[1][2], a[1][3]);
#pragma unroll
            for (int nb = 0; nb < 8; ++nb) {
                uint32_t b0, b1, b2, b3;
                ldsm_x4(b_base + (uint32_t)(nb * 16) * ROWB + kb, b0, b1, b2, b3);
                mma_bf16(acc[0][2 * nb],     a[0], b0, b2);
                mma_bf16(acc[0][2 * nb + 1], a[0], b1, b3);
                mma_bf16(acc[1][2 * nb],     a[1], b0, b2);
                mma_bf16(acc[1][2 * nb + 1], a[1], b1, b3);
            }
        }

        // ---- store next tile to buffer s^1 ----
        if (nvalid) {
            char* dst = smem + OFF_A + (uint32_t)(s ^ 1) * A_BUF
                      + (uint32_t)lrow * ROWB + (uint32_t)lhalf * 128u;
#pragma unroll
            for (int j = 0; j < 8; ++j)
                *reinterpret_cast<uint4*>(dst + 16 * j) =
                    *reinterpret_cast<uint4*>(&pk[4 * j]);
        }
        if (ii + 1 < T) {
            float t = ne2 + __shfl_xor_sync(0xffffffffu, ne2, 1);
            if (lhalf == 0) e2s[(s ^ 1) * 128 + lrow] = t;
        }

        // ---- fused distance epilogue ----
        {
            const float* e2c = e2s + s * 128;
            const int g = lane >> 2, t = lane & 3;
#pragma unroll
            for (int mi = 0; mi < 2; ++mi) {
#pragma unroll
                for (int h = 0; h < 2; ++h) {
                    const int row = warp_m * 32 + mi * 16 + h * 8 + g;
                    const long long grow = tile * kTM + row;
                    if (grow < nEmb) {
                        const float e2m = e2c[row];
                        float* orow = out + (size_t)grow * kP;
#pragma unroll
                        for (int nf = 0; nf < 16; ++nf) {
                            const int c = warp_n * 128 + nf * 8 + 2 * t;
                            const float2 pv = *reinterpret_cast<const float2*>(p2s + c);
                            float2 o;
                            o.x = negd(acc[mi][nf][h * 2 + 0], e2m + pv.x);
                            o.y = negd(acc[mi][nf][h * 2 + 1], e2m + pv.y);
                            __stcs(reinterpret_cast<float2*>(orow + c), o);
                        }
                    }
                }
            }
        }
        __syncthreads();
    }
}

extern "C" void kernel_launch(void* const* d_in, const int* in_sizes, int n_in,
                              void* d_out, int out_size)
{
    const float* emb   = (const float*)d_in[0];
    const float* proto = (const float*)d_in[1];
    float* out = (float*)d_out;

    const long long nEmb   = (long long)in_sizes[0] / kD;
    const long long nTiles = (nEmb + kTM - 1) / kTM;

    cudaFuncSetAttribute(proto_kernel, cudaFuncAttributeMaxDynamicSharedMemorySize,
                         (int)SMEM_TOTAL);
    int dev = 0;
    cudaGetDevice(&dev);
    int nsm = 148;
    cudaDeviceGetAttribute(&nsm, cudaDevAttrMultiProcessorCount, dev);
    const int gridx = (int)((nTiles < (long long)nsm) ? nTiles : (long long)nsm);

    proto_kernel<<<gridx, kThreads, SMEM_TOTAL>>>(emb, proto, out, nEmb, nTiles);
}